// round 1
// baseline (speedup 1.0000x reference)
#include <cuda_runtime.h>

#define EPS 1e-5f
typedef unsigned long long ull;

// ---------------- packed f32x2 helpers (B300 dual-rate FP32 path) ----------
__device__ __forceinline__ ull pack2(float x, float y) {
    ull r; asm("mov.b64 %0, {%1,%2};" : "=l"(r) : "f"(x), "f"(y)); return r;
}
__device__ __forceinline__ ull dup2(float x) { return pack2(x, x); }
__device__ __forceinline__ void unpack2(ull a, float& x, float& y) {
    asm("mov.b64 {%0,%1}, %2;" : "=f"(x), "=f"(y) : "l"(a));
}
__device__ __forceinline__ ull ffma2(ull a, ull b, ull c) {
    ull d; asm("fma.rn.f32x2 %0, %1, %2, %3;" : "=l"(d) : "l"(a), "l"(b), "l"(c));
    return d;
}
__device__ __forceinline__ ull relu2(ull a) {
    float x, y; unpack2(a, x, y);
    x = fmaxf(x, 0.f); y = fmaxf(y, 0.f);
    return pack2(x, y);
}

// ---------------- scratch (device globals: no allocs allowed) --------------
__device__ float g_pooled[2 * 768];
__device__ float g_xfeat[2 * 256];
__device__ float g_params[2 * 32 * 153];
__device__ float g_part[2 * 16 * 24 * 2];
__device__ float g_stats[2 * 16 * 2];   // (mean, rstd) per (b, group)

// ============================================================================
// Kernel A: GN1(x) + ReLU + spatial mean -> pooled (2,768)
// x: (2, 768, 8,8,8). 16 groups -> 48 ch/group, group = 24576 contiguous floats
// ============================================================================
__global__ void k_gn1_pool(const float* __restrict__ x,
                           const float* __restrict__ g1g,
                           const float* __restrict__ g1b) {
    int bg = blockIdx.x;            // 0..31
    int b = bg >> 4, g = bg & 15;
    const float* base = x + ((size_t)b * 768 + (size_t)g * 48) * 512;

    // pass 1: group mean / var
    float s = 0.f, ss = 0.f;
    const float4* b4 = (const float4*)base;
    for (int i = threadIdx.x; i < 6144; i += 256) {
        float4 v = b4[i];
        s  += v.x + v.y + v.z + v.w;
        ss += v.x * v.x + v.y * v.y + v.z * v.z + v.w * v.w;
    }
    __shared__ float rs[256], rss[256];
    rs[threadIdx.x] = s; rss[threadIdx.x] = ss;
    __syncthreads();
    for (int o = 128; o > 0; o >>= 1) {
        if (threadIdx.x < o) {
            rs[threadIdx.x]  += rs[threadIdx.x + o];
            rss[threadIdx.x] += rss[threadIdx.x + o];
        }
        __syncthreads();
    }
    __shared__ float s_mean, s_rstd;
    if (threadIdx.x == 0) {
        float mean = rs[0] * (1.f / 24576.f);
        float var  = rss[0] * (1.f / 24576.f) - mean * mean;
        s_mean = mean;
        s_rstd = rsqrtf(var + EPS);
    }
    __syncthreads();
    float mean = s_mean, rstd = s_rstd;

    // pass 2: per-channel mean of relu(normalized), warp per channel
    int warp = threadIdx.x >> 5, lane = threadIdx.x & 31;
    for (int c = warp; c < 48; c += 8) {
        int ch = g * 48 + c;
        float sc = rstd * g1g[ch];
        float sh = g1b[ch] - mean * sc;
        const float* cb = base + (size_t)c * 512;
        float acc = 0.f;
        for (int i = lane; i < 512; i += 32)
            acc += fmaxf(fmaf(cb[i], sc, sh), 0.f);
        for (int o = 16; o > 0; o >>= 1)
            acc += __shfl_down_sync(0xffffffffu, acc, o);
        if (lane == 0) g_pooled[b * 768 + ch] = acc * (1.f / 512.f);
    }
}

// ============================================================================
// Kernel B1: x_feat = pooled @ gap_w.T + gap_b   (2,256)
// ============================================================================
__global__ void k_xfeat(const float* __restrict__ gap_w,
                        const float* __restrict__ gap_b) {
    int b = blockIdx.x;
    int f = threadIdx.x;
    __shared__ float sp[768];
    for (int i = threadIdx.x; i < 768; i += 256) sp[i] = g_pooled[b * 768 + i];
    __syncthreads();
    float acc = gap_b[f];
    const float* wr = gap_w + (size_t)f * 768;
    for (int c = 0; c < 768; c++) acc = fmaf(sp[c], wr[c], acc);
    g_xfeat[b * 256 + f] = acc;
}

// ============================================================================
// Kernel B2: params[b,cls,p] = ctrl_w[p,:256]·x_feat[b] + ctrl_w[p,256:]·te[cls] + ctrl_b[p]
// ============================================================================
__global__ void k_params(const float* __restrict__ ctrl_w,
                         const float* __restrict__ ctrl_b,
                         const float* __restrict__ te) {
    int b = blockIdx.x >> 5, cls = blockIdx.x & 31;
    __shared__ float sxf[256], ste[256];
    sxf[threadIdx.x] = g_xfeat[b * 256 + threadIdx.x];
    ste[threadIdx.x] = te[cls * 256 + threadIdx.x];
    __syncthreads();
    int p = threadIdx.x;
    if (p < 153) {
        const float* wr = ctrl_w + (size_t)p * 512;
        float acc = ctrl_b[p];
        for (int f = 0; f < 256; f++) {
            acc = fmaf(wr[f], sxf[f], acc);
            acc = fmaf(wr[256 + f], ste[f], acc);
        }
        g_params[blockIdx.x * 153 + p] = acc;
    }
}

// ============================================================================
// Kernel C: GN2 partial sums over out (2,48,64^3), 16 groups -> 3 ch (786432
// contiguous floats) per group, 24 partial blocks per group
// ============================================================================
__global__ void k_gn2_part(const float* __restrict__ outp) {
    int bg = blockIdx.x / 24, part = blockIdx.x % 24;
    const float4* base = (const float4*)(outp + (size_t)bg * 786432) + (size_t)part * 8192;
    float s = 0.f, ss = 0.f;
    for (int i = threadIdx.x; i < 8192; i += 256) {
        float4 v = base[i];
        s  += v.x + v.y + v.z + v.w;
        ss += v.x * v.x + v.y * v.y + v.z * v.z + v.w * v.w;
    }
    __shared__ float rs[256], rss[256];
    rs[threadIdx.x] = s; rss[threadIdx.x] = ss;
    __syncthreads();
    for (int o = 128; o > 0; o >>= 1) {
        if (threadIdx.x < o) {
            rs[threadIdx.x]  += rs[threadIdx.x + o];
            rss[threadIdx.x] += rss[threadIdx.x + o];
        }
        __syncthreads();
    }
    if (threadIdx.x == 0) {
        g_part[blockIdx.x * 2]     = rs[0];
        g_part[blockIdx.x * 2 + 1] = rss[0];
    }
}

__global__ void k_gn2_fin() {
    int bg = threadIdx.x;   // 32 threads
    float s = 0.f, ss = 0.f;
    for (int p = 0; p < 24; p++) {
        s  += g_part[(bg * 24 + p) * 2];
        ss += g_part[(bg * 24 + p) * 2 + 1];
    }
    float mean = s * (1.f / 786432.f);
    float var  = ss * (1.f / 786432.f) - mean * mean;
    g_stats[bg * 2]     = mean;
    g_stats[bg * 2 + 1] = rsqrtf(var + EPS);
}

// ============================================================================
// Kernel E: fused GN2+ReLU -> h0 (48->8) -> 32x per-class MLP 8->8->8->1
// V=8 voxels per thread as 4x f32x2; all weights in smem pre-duplicated (w,w)
// ============================================================================
__global__ void __launch_bounds__(128, 2)
k_main(const float* __restrict__ outp,
       const float* __restrict__ g2g, const float* __restrict__ g2b,
       const float* __restrict__ pre_w, const float* __restrict__ pre_b,
       float* __restrict__ dst) {
    __shared__ ull s_params[32 * 153];   // 39168 B
    __shared__ ull s_prew[8 * 48];       //  3072 B
    __shared__ ull s_preb[8];
    __shared__ ull s_scale[48], s_shift[48];

    int b = blockIdx.x >> 8;          // 256 chunks per batch
    int chunk = blockIdx.x & 255;
    int t = threadIdx.x;

    for (int i = t; i < 4896; i += 128) s_params[i] = dup2(g_params[b * 4896 + i]);
    for (int i = t; i < 384;  i += 128) s_prew[i]   = dup2(pre_w[i]);
    if (t < 8) s_preb[t] = dup2(pre_b[t]);
    if (t < 48) {
        int g = t / 3;
        float mean = g_stats[(b * 16 + g) * 2];
        float rstd = g_stats[(b * 16 + g) * 2 + 1];
        float sc = rstd * g2g[t];
        s_scale[t] = dup2(sc);
        s_shift[t] = dup2(g2b[t] - mean * sc);
    }
    __syncthreads();

    // float2-unit index within this batch's 131072 float2's
    int u0 = chunk * 512 + t;                          // + i*128, i=0..3
    const ull* src = (const ull*)outp + (size_t)b * 48 * 131072;

    // h0[o] accumulation over 48 input channels
    ull h0[8][4];
#pragma unroll
    for (int o = 0; o < 8; o++)
#pragma unroll
        for (int i = 0; i < 4; i++) h0[o][i] = s_preb[o];

    for (int c = 0; c < 48; c++) {
        ull sc = s_scale[c], sh = s_shift[c];
        const ull* cs = src + (size_t)c * 131072 + u0;
        ull gv[4];
#pragma unroll
        for (int i = 0; i < 4; i++)
            gv[i] = relu2(ffma2(cs[i * 128], sc, sh));
#pragma unroll
        for (int o = 0; o < 8; o++) {
            ull w = s_prew[o * 48 + c];
#pragma unroll
            for (int i = 0; i < 4; i++) h0[o][i] = ffma2(w, gv[i], h0[o][i]);
        }
    }

    ull* dbase = (ull*)dst + (size_t)b * 32 * 131072 + u0;

    for (int cls = 0; cls < 32; cls++) {
        const ull* P = s_params + cls * 153;
        // ---- layer 1: t1 = relu(W1 h0 + b1), bias folded into k=0 ----
        ull t1[8][4];
#pragma unroll
        for (int j = 0; j < 8; j++) {
            ull bias = P[136 + j];
            ull w0 = P[j * 8];
#pragma unroll
            for (int i = 0; i < 4; i++) t1[j][i] = ffma2(w0, h0[0][i], bias);
        }
#pragma unroll
        for (int k = 1; k < 8; k++) {
#pragma unroll
            for (int j = 0; j < 8; j++) {
                ull w = P[j * 8 + k];
#pragma unroll
                for (int i = 0; i < 4; i++) t1[j][i] = ffma2(w, h0[k][i], t1[j][i]);
            }
        }
#pragma unroll
        for (int j = 0; j < 8; j++)
#pragma unroll
            for (int i = 0; i < 4; i++) t1[j][i] = relu2(t1[j][i]);

        // ---- layers 2+3 folded: y += w3[j] * relu(W2[j]·t1 + b2[j]) ----
        ull y[4];
        ull b3 = P[152];
#pragma unroll
        for (int i = 0; i < 4; i++) y[i] = b3;
#pragma unroll
        for (int j = 0; j < 8; j++) {
            ull t2[4];
            ull bias = P[144 + j];
            ull w0 = P[64 + j * 8];
#pragma unroll
            for (int i = 0; i < 4; i++) t2[i] = ffma2(w0, t1[0][i], bias);
#pragma unroll
            for (int k = 1; k < 8; k++) {
                ull w = P[64 + j * 8 + k];
#pragma unroll
                for (int i = 0; i < 4; i++) t2[i] = ffma2(w, t1[k][i], t2[i]);
            }
            ull w3 = P[128 + j];
#pragma unroll
            for (int i = 0; i < 4; i++) y[i] = ffma2(w3, relu2(t2[i]), y[i]);
        }

        ull* dp = dbase + (size_t)cls * 131072;
#pragma unroll
        for (int i = 0; i < 4; i++) dp[i * 128] = y[i];
    }
}

// ============================================================================
extern "C" void kernel_launch(void* const* d_in, const int* in_sizes, int n_in,
                              void* d_out, int out_size) {
    const float* x      = (const float*)d_in[0];
    const float* outp   = (const float*)d_in[1];
    const float* te     = (const float*)d_in[2];
    const float* gn1_g  = (const float*)d_in[3];
    const float* gn1_b  = (const float*)d_in[4];
    const float* gap_w  = (const float*)d_in[5];
    const float* gap_b  = (const float*)d_in[6];
    const float* ctrl_w = (const float*)d_in[7];
    const float* ctrl_b = (const float*)d_in[8];
    const float* gn2_g  = (const float*)d_in[9];
    const float* gn2_b  = (const float*)d_in[10];
    const float* pre_w  = (const float*)d_in[11];
    const float* pre_b  = (const float*)d_in[12];
    float* dst = (float*)d_out;

    // big streaming stats first (longest independent kernel)
    k_gn2_part<<<768, 256>>>(outp);
    k_gn1_pool<<<32, 256>>>(x, gn1_g, gn1_b);
    k_xfeat<<<2, 256>>>(gap_w, gap_b);
    k_params<<<64, 256>>>(ctrl_w, ctrl_b, te);
    k_gn2_fin<<<1, 32>>>();
    k_main<<<512, 128>>>(outp, gn2_g, gn2_b, pre_w, pre_b, dst);
}

// round 3
// speedup vs baseline: 1.4031x; 1.4031x over previous
#include <cuda_runtime.h>

#define EPS 1e-5f
typedef unsigned long long ull;

// ---------------- packed f32x2 helpers (B300 dual-rate FP32 path) ----------
__device__ __forceinline__ ull pack2(float x, float y) {
    ull r; asm("mov.b64 %0, {%1,%2};" : "=l"(r) : "f"(x), "f"(y)); return r;
}
__device__ __forceinline__ ull dup2(float x) { return pack2(x, x); }
__device__ __forceinline__ void unpack2(ull a, float& x, float& y) {
    asm("mov.b64 {%0,%1}, %2;" : "=f"(x), "=f"(y) : "l"(a));
}
__device__ __forceinline__ ull ffma2(ull a, ull b, ull c) {
    ull d; asm("fma.rn.f32x2 %0, %1, %2, %3;" : "=l"(d) : "l"(a), "l"(b), "l"(c));
    return d;
}
__device__ __forceinline__ ull relu2(ull a) {
    float x, y; unpack2(a, x, y);
    x = fmaxf(x, 0.f); y = fmaxf(y, 0.f);
    return pack2(x, y);
}

// ---------------- scratch (device globals: no allocs allowed) --------------
__device__ float g_pooled[2 * 768];
__device__ float g_xfeat[2 * 256];
__device__ float g_params[2 * 32 * 153];
__device__ float g_part[2 * 16 * 24 * 2];
__device__ float g_stats[2 * 16 * 2];   // (mean, rstd) per (b, group)

// ============================================================================
// Kernel A: GN1(x) + ReLU + spatial mean -> pooled (2,768)
// ============================================================================
__global__ void k_gn1_pool(const float* __restrict__ x,
                           const float* __restrict__ g1g,
                           const float* __restrict__ g1b) {
    int bg = blockIdx.x;            // 0..31
    int b = bg >> 4, g = bg & 15;
    const float* base = x + ((size_t)b * 768 + (size_t)g * 48) * 512;

    float s = 0.f, ss = 0.f;
    const float4* b4 = (const float4*)base;
    for (int i = threadIdx.x; i < 6144; i += 256) {
        float4 v = b4[i];
        s  += v.x + v.y + v.z + v.w;
        ss += v.x * v.x + v.y * v.y + v.z * v.z + v.w * v.w;
    }
    __shared__ float rs[256], rss[256];
    rs[threadIdx.x] = s; rss[threadIdx.x] = ss;
    __syncthreads();
    for (int o = 128; o > 0; o >>= 1) {
        if (threadIdx.x < o) {
            rs[threadIdx.x]  += rs[threadIdx.x + o];
            rss[threadIdx.x] += rss[threadIdx.x + o];
        }
        __syncthreads();
    }
    __shared__ float s_mean, s_rstd;
    if (threadIdx.x == 0) {
        float mean = rs[0] * (1.f / 24576.f);
        float var  = rss[0] * (1.f / 24576.f) - mean * mean;
        s_mean = mean;
        s_rstd = rsqrtf(var + EPS);
    }
    __syncthreads();
    float mean = s_mean, rstd = s_rstd;

    int warp = threadIdx.x >> 5, lane = threadIdx.x & 31;
    for (int c = warp; c < 48; c += 8) {
        int ch = g * 48 + c;
        float sc = rstd * g1g[ch];
        float sh = g1b[ch] - mean * sc;
        const float* cb = base + (size_t)c * 512;
        float acc = 0.f;
        for (int i = lane; i < 512; i += 32)
            acc += fmaxf(fmaf(cb[i], sc, sh), 0.f);
        for (int o = 16; o > 0; o >>= 1)
            acc += __shfl_down_sync(0xffffffffu, acc, o);
        if (lane == 0) g_pooled[b * 768 + ch] = acc * (1.f / 512.f);
    }
}

// ============================================================================
// Kernel B1: x_feat = pooled @ gap_w.T + gap_b   (2,256)
// warp-per-output, coalesced row reads, shfl reduce
// ============================================================================
__global__ void k_xfeat(const float* __restrict__ gap_w,
                        const float* __restrict__ gap_b) {
    int b   = blockIdx.x >> 3;        // 16 blocks: 8 per batch
    int sub = blockIdx.x & 7;
    int warp = threadIdx.x >> 5, lane = threadIdx.x & 31;

    __shared__ float sp[768];
    for (int i = threadIdx.x; i < 768; i += 256) sp[i] = g_pooled[b * 768 + i];
    __syncthreads();

    for (int q = 0; q < 4; q++) {
        int f = sub * 32 + q * 8 + warp;
        const float* wr = gap_w + (size_t)f * 768;
        float acc = 0.f;
        for (int i = lane; i < 768; i += 32)
            acc = fmaf(wr[i], sp[i], acc);
        for (int o = 16; o > 0; o >>= 1)
            acc += __shfl_down_sync(0xffffffffu, acc, o);
        if (lane == 0) g_xfeat[b * 256 + f] = acc + gap_b[f];
    }
}

// ============================================================================
// Kernel B2: params[b,cls,p] — warp-per-p, coalesced ctrl_w rows
// ============================================================================
__global__ void k_params(const float* __restrict__ ctrl_w,
                         const float* __restrict__ ctrl_b,
                         const float* __restrict__ te) {
    int b = blockIdx.x >> 5, cls = blockIdx.x & 31;
    int warp = threadIdx.x >> 5, lane = threadIdx.x & 31;

    __shared__ float sv[512];         // concat(x_feat[b], te[cls]) matches ctrl_w rows
    // FIX (round 2 bug): block has 256 threads; each writes BOTH halves.
    sv[threadIdx.x]       = g_xfeat[b * 256 + threadIdx.x];
    sv[256 + threadIdx.x] = te[cls * 256 + threadIdx.x];
    __syncthreads();

    for (int p = warp; p < 153; p += 8) {
        const float* wr = ctrl_w + (size_t)p * 512;
        float acc = 0.f;
#pragma unroll
        for (int it = 0; it < 16; it++) {
            int f = it * 32 + lane;
            acc = fmaf(wr[f], sv[f], acc);
        }
        for (int o = 16; o > 0; o >>= 1)
            acc += __shfl_down_sync(0xffffffffu, acc, o);
        if (lane == 0) g_params[blockIdx.x * 153 + p] = acc + ctrl_b[p];
    }
}

// ============================================================================
// Kernel C: GN2 partial sums over out (2,48,64^3)
// ============================================================================
__global__ void k_gn2_part(const float* __restrict__ outp) {
    int bg = blockIdx.x / 24, part = blockIdx.x % 24;
    const float4* base = (const float4*)(outp + (size_t)bg * 786432) + (size_t)part * 8192;
    float s = 0.f, ss = 0.f;
    for (int i = threadIdx.x; i < 8192; i += 256) {
        float4 v = base[i];
        s  += v.x + v.y + v.z + v.w;
        ss += v.x * v.x + v.y * v.y + v.z * v.z + v.w * v.w;
    }
    __shared__ float rs[256], rss[256];
    rs[threadIdx.x] = s; rss[threadIdx.x] = ss;
    __syncthreads();
    for (int o = 128; o > 0; o >>= 1) {
        if (threadIdx.x < o) {
            rs[threadIdx.x]  += rs[threadIdx.x + o];
            rss[threadIdx.x] += rss[threadIdx.x + o];
        }
        __syncthreads();
    }
    if (threadIdx.x == 0) {
        g_part[blockIdx.x * 2]     = rs[0];
        g_part[blockIdx.x * 2 + 1] = rss[0];
    }
}

__global__ void k_gn2_fin() {
    int bg = threadIdx.x;   // 32 threads
    float s = 0.f, ss = 0.f;
    for (int p = 0; p < 24; p++) {
        s  += g_part[(bg * 24 + p) * 2];
        ss += g_part[(bg * 24 + p) * 2 + 1];
    }
    float mean = s * (1.f / 786432.f);
    float var  = ss * (1.f / 786432.f) - mean * mean;
    g_stats[bg * 2]     = mean;
    g_stats[bg * 2 + 1] = rsqrtf(var + EPS);
}

// ============================================================================
// Kernel E: fused GN2+ReLU -> h0 (48->8) -> 32x per-class MLP 8->8->8->1
// V=2 ull (4 voxels) per thread, 256-thread CTAs, 16 warps/SM for latency hiding
// ============================================================================
__global__ void __launch_bounds__(256, 2)
k_main(const float* __restrict__ outp,
       const float* __restrict__ g2g, const float* __restrict__ g2b,
       const float* __restrict__ pre_w, const float* __restrict__ pre_b,
       float* __restrict__ dst) {
    __shared__ ull s_params[32 * 153];   // 39168 B
    __shared__ ull s_prew[8 * 48];       //  3072 B
    __shared__ ull s_preb[8];
    __shared__ ull s_scale[48], s_shift[48];

    int b = blockIdx.x >> 8;          // 256 chunks per batch
    int chunk = blockIdx.x & 255;
    int t = threadIdx.x;

    for (int i = t; i < 4896; i += 256) s_params[i] = dup2(g_params[b * 4896 + i]);
    for (int i = t; i < 384;  i += 256) s_prew[i]   = dup2(pre_w[i]);
    if (t < 8) s_preb[t] = dup2(pre_b[t]);
    if (t >= 32 && t < 80) {
        int c = t - 32;
        int g = c / 3;
        float mean = g_stats[(b * 16 + g) * 2];
        float rstd = g_stats[(b * 16 + g) * 2 + 1];
        float sc = rstd * g2g[c];
        s_scale[c] = dup2(sc);
        s_shift[c] = dup2(g2b[c] - mean * sc);
    }
    __syncthreads();

    // each thread handles float2 units u0 and u0+256 of this batch
    int u0 = chunk * 512 + t;
    const ull* src = (const ull*)outp + (size_t)b * 48 * 131072 + u0;

    ull h0[8][2];
#pragma unroll
    for (int o = 0; o < 8; o++) {
        h0[o][0] = s_preb[o];
        h0[o][1] = s_preb[o];
    }

    // GN2 + ReLU + h0 = pre_w·g, with next-channel prefetch
    ull n0 = src[0], n1 = src[256];
    for (int c = 0; c < 48; c++) {
        ull v0 = n0, v1 = n1;
        if (c < 47) {
            const ull* nx = src + (size_t)(c + 1) * 131072;
            n0 = nx[0]; n1 = nx[256];
        }
        ull sc = s_scale[c], sh = s_shift[c];
        ull g0 = relu2(ffma2(v0, sc, sh));
        ull g1 = relu2(ffma2(v1, sc, sh));
#pragma unroll
        for (int o = 0; o < 8; o++) {
            ull w = s_prew[o * 48 + c];
            h0[o][0] = ffma2(w, g0, h0[o][0]);
            h0[o][1] = ffma2(w, g1, h0[o][1]);
        }
    }

    ull* dbase = (ull*)dst + (size_t)b * 32 * 131072 + u0;

    for (int cls = 0; cls < 32; cls++) {
        const ull* P = s_params + cls * 153;
        // ---- layer 1: t1 = relu(W1 h0 + b1), bias folded into k=0 ----
        ull t1[8][2];
#pragma unroll
        for (int j = 0; j < 8; j++) {
            ull bias = P[136 + j];
            ull w0 = P[j * 8];
            t1[j][0] = ffma2(w0, h0[0][0], bias);
            t1[j][1] = ffma2(w0, h0[0][1], bias);
        }
#pragma unroll
        for (int k = 1; k < 8; k++) {
#pragma unroll
            for (int j = 0; j < 8; j++) {
                ull w = P[j * 8 + k];
                t1[j][0] = ffma2(w, h0[k][0], t1[j][0]);
                t1[j][1] = ffma2(w, h0[k][1], t1[j][1]);
            }
        }
#pragma unroll
        for (int j = 0; j < 8; j++) {
            t1[j][0] = relu2(t1[j][0]);
            t1[j][1] = relu2(t1[j][1]);
        }

        // ---- layers 2+3 folded: y += w3[j] * relu(W2[j]·t1 + b2[j]) ----
        ull y0 = P[152], y1 = P[152];
#pragma unroll
        for (int j = 0; j < 8; j++) {
            ull bias = P[144 + j];
            ull w0 = P[64 + j * 8];
            ull t20 = ffma2(w0, t1[0][0], bias);
            ull t21 = ffma2(w0, t1[0][1], bias);
#pragma unroll
            for (int k = 1; k < 8; k++) {
                ull w = P[64 + j * 8 + k];
                t20 = ffma2(w, t1[k][0], t20);
                t21 = ffma2(w, t1[k][1], t21);
            }
            ull w3 = P[128 + j];
            y0 = ffma2(w3, relu2(t20), y0);
            y1 = ffma2(w3, relu2(t21), y1);
        }

        ull* dp = dbase + (size_t)cls * 131072;
        dp[0]   = y0;
        dp[256] = y1;
    }
}

// ============================================================================
extern "C" void kernel_launch(void* const* d_in, const int* in_sizes, int n_in,
                              void* d_out, int out_size) {
    const float* x      = (const float*)d_in[0];
    const float* outp   = (const float*)d_in[1];
    const float* te     = (const float*)d_in[2];
    const float* gn1_g  = (const float*)d_in[3];
    const float* gn1_b  = (const float*)d_in[4];
    const float* gap_w  = (const float*)d_in[5];
    const float* gap_b  = (const float*)d_in[6];
    const float* ctrl_w = (const float*)d_in[7];
    const float* ctrl_b = (const float*)d_in[8];
    const float* gn2_g  = (const float*)d_in[9];
    const float* gn2_b  = (const float*)d_in[10];
    const float* pre_w  = (const float*)d_in[11];
    const float* pre_b  = (const float*)d_in[12];
    float* dst = (float*)d_out;

    k_gn2_part<<<768, 256>>>(outp);
    k_gn1_pool<<<32, 256>>>(x, gn1_g, gn1_b);
    k_xfeat<<<16, 256>>>(gap_w, gap_b);
    k_params<<<64, 256>>>(ctrl_w, ctrl_b, te);
    k_gn2_fin<<<1, 32>>>();
    k_main<<<512, 256>>>(outp, gn2_g, gn2_b, pre_w, pre_b, dst);
}

// round 4
// speedup vs baseline: 1.6636x; 1.1857x over previous
#include <cuda_runtime.h>

#define EPS 1e-5f
typedef unsigned long long ull;

// ---------------- packed f32x2 helpers (B300 dual-rate FP32 path) ----------
__device__ __forceinline__ ull pack2(float x, float y) {
    ull r; asm("mov.b64 %0, {%1,%2};" : "=l"(r) : "f"(x), "f"(y)); return r;
}
__device__ __forceinline__ ull dup2(float x) { return pack2(x, x); }
__device__ __forceinline__ void unpack2(ull a, float& x, float& y) {
    asm("mov.b64 {%0,%1}, %2;" : "=f"(x), "=f"(y) : "l"(a));
}
__device__ __forceinline__ ull ffma2(ull a, ull b, ull c) {
    ull d; asm("fma.rn.f32x2 %0, %1, %2, %3;" : "=l"(d) : "l"(a), "l"(b), "l"(c));
    return d;
}
__device__ __forceinline__ ull relu2(ull a) {
    float x, y; unpack2(a, x, y);
    x = fmaxf(x, 0.f); y = fmaxf(y, 0.f);
    return pack2(x, y);
}

// ---------------- scratch (device globals: no allocs allowed) --------------
__device__ float g_pooled[2 * 768];
__device__ float g_xfeat[2 * 256];
__device__ float g_G1[2 * 153];     // ctrl_w[:, :256] @ x_feat + ctrl_b
__device__ float g_G2[32 * 153];    // ctrl_w[:, 256:] @ te
__device__ float g_part[2 * 16 * 24 * 2];
__device__ float g_stats[2 * 16 * 2];   // (mean, rstd) per (b, group)

// ============================================================================
// Kernel A: GN1(x) + ReLU + spatial mean -> pooled (2,768)
// ============================================================================
__global__ void k_gn1_pool(const float* __restrict__ x,
                           const float* __restrict__ g1g,
                           const float* __restrict__ g1b) {
    int bg = blockIdx.x;            // 0..31
    int b = bg >> 4, g = bg & 15;
    const float* base = x + ((size_t)b * 768 + (size_t)g * 48) * 512;

    float s = 0.f, ss = 0.f;
    const float4* b4 = (const float4*)base;
    for (int i = threadIdx.x; i < 6144; i += 256) {
        float4 v = b4[i];
        s  += v.x + v.y + v.z + v.w;
        ss += v.x * v.x + v.y * v.y + v.z * v.z + v.w * v.w;
    }
    __shared__ float rs[256], rss[256];
    rs[threadIdx.x] = s; rss[threadIdx.x] = ss;
    __syncthreads();
    for (int o = 128; o > 0; o >>= 1) {
        if (threadIdx.x < o) {
            rs[threadIdx.x]  += rs[threadIdx.x + o];
            rss[threadIdx.x] += rss[threadIdx.x + o];
        }
        __syncthreads();
    }
    __shared__ float s_mean, s_rstd;
    if (threadIdx.x == 0) {
        float mean = rs[0] * (1.f / 24576.f);
        float var  = rss[0] * (1.f / 24576.f) - mean * mean;
        s_mean = mean;
        s_rstd = rsqrtf(var + EPS);
    }
    __syncthreads();
    float mean = s_mean, rstd = s_rstd;

    int warp = threadIdx.x >> 5, lane = threadIdx.x & 31;
    for (int c = warp; c < 48; c += 8) {
        int ch = g * 48 + c;
        float sc = rstd * g1g[ch];
        float sh = g1b[ch] - mean * sc;
        const float* cb = base + (size_t)c * 512;
        float acc = 0.f;
        for (int i = lane; i < 512; i += 32)
            acc += fmaxf(fmaf(cb[i], sc, sh), 0.f);
        for (int o = 16; o > 0; o >>= 1)
            acc += __shfl_down_sync(0xffffffffu, acc, o);
        if (lane == 0) g_pooled[b * 768 + ch] = acc * (1.f / 512.f);
    }
}

// ============================================================================
// Kernel B1: x_feat = pooled @ gap_w.T + gap_b   (2,256)
// ============================================================================
__global__ void k_xfeat(const float* __restrict__ gap_w,
                        const float* __restrict__ gap_b) {
    int b   = blockIdx.x >> 3;        // 16 blocks: 8 per batch
    int sub = blockIdx.x & 7;
    int warp = threadIdx.x >> 5, lane = threadIdx.x & 31;

    __shared__ float sp[768];
    for (int i = threadIdx.x; i < 768; i += 256) sp[i] = g_pooled[b * 768 + i];
    __syncthreads();

    for (int q = 0; q < 4; q++) {
        int f = sub * 32 + q * 8 + warp;
        const float* wr = gap_w + (size_t)f * 768;
        float acc = 0.f;
        for (int i = lane; i < 768; i += 32)
            acc = fmaf(wr[i], sp[i], acc);
        for (int o = 16; o > 0; o >>= 1)
            acc += __shfl_down_sync(0xffffffffu, acc, o);
        if (lane == 0) g_xfeat[b * 256 + f] = acc + gap_b[f];
    }
}

// ============================================================================
// Kernel B2: G1[b,p] = ctrl_w[p,:256]·x_feat[b] + ctrl_b[p]   (blocks 0,1)
//            G2[c,p] = ctrl_w[p,256:]·te[c]                   (blocks 2..33)
// 5x less work than the old full (b,cls,p) expansion; ctrl_w read once.
// ============================================================================
__global__ void k_gparams(const float* __restrict__ ctrl_w,
                          const float* __restrict__ ctrl_b,
                          const float* __restrict__ te) {
    int blk = blockIdx.x;             // 0..33
    int warp = threadIdx.x >> 5, lane = threadIdx.x & 31;

    __shared__ float sv[256];
    const float* wbase;
    float* dst;
    bool addb;
    if (blk < 2) {
        sv[threadIdx.x] = g_xfeat[blk * 256 + threadIdx.x];
        wbase = ctrl_w;                 // rows of first 256 cols
        dst = g_G1 + blk * 153;
        addb = true;
    } else {
        int c = blk - 2;
        sv[threadIdx.x] = te[c * 256 + threadIdx.x];
        wbase = ctrl_w + 256;           // rows of last 256 cols
        dst = g_G2 + c * 153;
        addb = false;
    }
    __syncthreads();

    for (int p = warp; p < 153; p += 8) {
        const float* wr = wbase + (size_t)p * 512;
        float acc = 0.f;
#pragma unroll
        for (int it = 0; it < 8; it++) {
            int f = it * 32 + lane;
            acc = fmaf(wr[f], sv[f], acc);
        }
        for (int o = 16; o > 0; o >>= 1)
            acc += __shfl_down_sync(0xffffffffu, acc, o);
        if (lane == 0) dst[p] = addb ? (acc + ctrl_b[p]) : acc;
    }
}

// ============================================================================
// Kernel C: GN2 partial sums over out (2,48,64^3)
// ============================================================================
__global__ void k_gn2_part(const float* __restrict__ outp) {
    int bg = blockIdx.x / 24, part = blockIdx.x % 24;
    const float4* base = (const float4*)(outp + (size_t)bg * 786432) + (size_t)part * 8192;
    float s = 0.f, ss = 0.f;
    for (int i = threadIdx.x; i < 8192; i += 256) {
        float4 v = base[i];
        s  += v.x + v.y + v.z + v.w;
        ss += v.x * v.x + v.y * v.y + v.z * v.z + v.w * v.w;
    }
    __shared__ float rs[256], rss[256];
    rs[threadIdx.x] = s; rss[threadIdx.x] = ss;
    __syncthreads();
    for (int o = 128; o > 0; o >>= 1) {
        if (threadIdx.x < o) {
            rs[threadIdx.x]  += rs[threadIdx.x + o];
            rss[threadIdx.x] += rss[threadIdx.x + o];
        }
        __syncthreads();
    }
    if (threadIdx.x == 0) {
        g_part[blockIdx.x * 2]     = rs[0];
        g_part[blockIdx.x * 2 + 1] = rss[0];
    }
}

__global__ void k_gn2_fin() {
    int bg = threadIdx.x;   // 32 threads
    float s = 0.f, ss = 0.f;
    for (int p = 0; p < 24; p++) {
        s  += g_part[(bg * 24 + p) * 2];
        ss += g_part[(bg * 24 + p) * 2 + 1];
    }
    float mean = s * (1.f / 786432.f);
    float var  = ss * (1.f / 786432.f) - mean * mean;
    g_stats[bg * 2]     = mean;
    g_stats[bg * 2 + 1] = rsqrtf(var + EPS);
}

// ============================================================================
// Kernel E: fused GN2+ReLU -> h0 (48->8) -> 32x per-class MLP 8->8->8->1
// V=2 ull/thread, 256-thread CTAs, occ 2 (4 warps/SMSP).
// Weights duplicated (w,w) in smem; adjacent pairs fetched as LDS.128
// (ulonglong2) to halve shared-load issue slots. Class stride padded to 154
// for 16B alignment.
// ============================================================================
__global__ void __launch_bounds__(256, 2)
k_main(const float* __restrict__ outp,
       const float* __restrict__ g2g, const float* __restrict__ g2b,
       const float* __restrict__ pre_w, const float* __restrict__ pre_b,
       float* __restrict__ dst) {
    __shared__ ull s_params[32 * 154];         // 39424 B (pad 154 -> 16B align)
    __shared__ ull s_prew[48 * 8];             // transposed [c][o], 3072 B
    __shared__ ull s_preb[8];
    __shared__ ulonglong2 s_gn[48];            // .x=scale .y=shift (dup2'd)

    int b = blockIdx.x >> 8;          // 256 chunks per batch
    int chunk = blockIdx.x & 255;
    int t = threadIdx.x;

    // params assembly: s_params[cls*154+p] = dup2(G1[b,p] + G2[cls,p])
    for (int i = t; i < 32 * 154; i += 256) {
        int cls = i / 154, p = i - cls * 154;
        if (p < 153)
            s_params[i] = dup2(g_G1[b * 153 + p] + g_G2[cls * 153 + p]);
    }
    // pre_w transposed: [c][o]
    for (int i = t; i < 384; i += 256) {
        int c = i >> 3, o = i & 7;
        s_prew[i] = dup2(pre_w[o * 48 + c]);
    }
    if (t < 8) s_preb[t] = dup2(pre_b[t]);
    if (t >= 32 && t < 80) {
        int c = t - 32;
        int g = c / 3;
        float mean = g_stats[(b * 16 + g) * 2];
        float rstd = g_stats[(b * 16 + g) * 2 + 1];
        float sc = rstd * g2g[c];
        s_gn[c].x = dup2(sc);
        s_gn[c].y = dup2(g2b[c] - mean * sc);
    }
    __syncthreads();

    // each thread handles float2 units u0 and u0+256 of this batch
    int u0 = chunk * 512 + t;
    const ull* src = (const ull*)outp + (size_t)b * 48 * 131072 + u0;

    ull h0[8][2];
#pragma unroll
    for (int o = 0; o < 8; o++) {
        h0[o][0] = s_preb[o];
        h0[o][1] = s_preb[o];
    }

    // GN2 + ReLU + h0 = pre_w·g, next-channel prefetch, paired weight loads
    ull n0 = src[0], n1 = src[256];
    for (int c = 0; c < 48; c++) {
        ull v0 = n0, v1 = n1;
        if (c < 47) {
            const ull* nx = src + (size_t)(c + 1) * 131072;
            n0 = nx[0]; n1 = nx[256];
        }
        ulonglong2 gn = s_gn[c];
        ull g0 = relu2(ffma2(v0, gn.x, gn.y));
        ull g1 = relu2(ffma2(v1, gn.x, gn.y));
        const ulonglong2* W = (const ulonglong2*)(s_prew + c * 8);
#pragma unroll
        for (int oo = 0; oo < 4; oo++) {
            ulonglong2 w2 = W[oo];
            h0[2 * oo][0]     = ffma2(w2.x, g0, h0[2 * oo][0]);
            h0[2 * oo][1]     = ffma2(w2.x, g1, h0[2 * oo][1]);
            h0[2 * oo + 1][0] = ffma2(w2.y, g0, h0[2 * oo + 1][0]);
            h0[2 * oo + 1][1] = ffma2(w2.y, g1, h0[2 * oo + 1][1]);
        }
    }

    ull* dbase = (ull*)dst + (size_t)b * 32 * 131072 + u0;

    for (int cls = 0; cls < 32; cls++) {
        const ull* P = s_params + cls * 154;
        const ulonglong2* P2 = (const ulonglong2*)P;   // 16B aligned (154*8*cls)

        // ---- layer 1: t1 = relu(W1 h0 + b1) ----
        ull t1[8][2];
#pragma unroll
        for (int j = 0; j < 8; j++) {
            ull bias = P[136 + j];
            t1[j][0] = bias;
            t1[j][1] = bias;
        }
#pragma unroll
        for (int kk = 0; kk < 4; kk++) {
#pragma unroll
            for (int j = 0; j < 8; j++) {
                ulonglong2 w2 = P2[j * 4 + kk];        // W1[j][2kk], W1[j][2kk+1]
                t1[j][0] = ffma2(w2.x, h0[2 * kk][0],     t1[j][0]);
                t1[j][1] = ffma2(w2.x, h0[2 * kk][1],     t1[j][1]);
                t1[j][0] = ffma2(w2.y, h0[2 * kk + 1][0], t1[j][0]);
                t1[j][1] = ffma2(w2.y, h0[2 * kk + 1][1], t1[j][1]);
            }
        }
#pragma unroll
        for (int j = 0; j < 8; j++) {
            t1[j][0] = relu2(t1[j][0]);
            t1[j][1] = relu2(t1[j][1]);
        }

        // ---- layers 2+3 folded: y += w3[j] * relu(W2[j]·t1 + b2[j]) ----
        ull y0 = P[152], y1 = P[152];
#pragma unroll
        for (int j = 0; j < 8; j++) {
            ull bias = P[144 + j];
            ull t20 = bias, t21 = bias;
#pragma unroll
            for (int kk = 0; kk < 4; kk++) {
                ulonglong2 w2 = P2[32 + j * 4 + kk];   // W2[j][2kk], W2[j][2kk+1]
                t20 = ffma2(w2.x, t1[2 * kk][0],     t20);
                t21 = ffma2(w2.x, t1[2 * kk][1],     t21);
                t20 = ffma2(w2.y, t1[2 * kk + 1][0], t20);
                t21 = ffma2(w2.y, t1[2 * kk + 1][1], t21);
            }
            ull w3 = P[128 + j];
            y0 = ffma2(w3, relu2(t20), y0);
            y1 = ffma2(w3, relu2(t21), y1);
        }

        ull* dp = dbase + (size_t)cls * 131072;
        dp[0]   = y0;
        dp[256] = y1;
    }
}

// ============================================================================
extern "C" void kernel_launch(void* const* d_in, const int* in_sizes, int n_in,
                              void* d_out, int out_size) {
    const float* x      = (const float*)d_in[0];
    const float* outp   = (const float*)d_in[1];
    const float* te     = (const float*)d_in[2];
    const float* gn1_g  = (const float*)d_in[3];
    const float* gn1_b  = (const float*)d_in[4];
    const float* gap_w  = (const float*)d_in[5];
    const float* gap_b  = (const float*)d_in[6];
    const float* ctrl_w = (const float*)d_in[7];
    const float* ctrl_b = (const float*)d_in[8];
    const float* gn2_g  = (const float*)d_in[9];
    const float* gn2_b  = (const float*)d_in[10];
    const float* pre_w  = (const float*)d_in[11];
    const float* pre_b  = (const float*)d_in[12];
    float* dst = (float*)d_out;

    k_gn2_part<<<768, 256>>>(outp);
    k_gn1_pool<<<32, 256>>>(x, gn1_g, gn1_b);
    k_xfeat<<<16, 256>>>(gap_w, gap_b);
    k_gparams<<<34, 256>>>(ctrl_w, ctrl_b, te);
    k_gn2_fin<<<1, 32>>>();
    k_main<<<512, 256>>>(outp, gn2_g, gn2_b, pre_w, pre_b, dst);
}